// round 9
// baseline (speedup 1.0000x reference)
#include <cuda_runtime.h>
#include <cuda_bf16.h>
#include <cstdint>
#include <cstddef>

#define HEADS 24
#define HDIM  128
#define LQ    13824
#define LKV   30720
#define NITER 108          // 27 kv tiles * 4 chunks of 64 keys

__device__ __align__(128) float g_Qt[(size_t)HEADS * LQ  * HDIM];
__device__ __align__(128) float g_Kt[(size_t)HEADS * LKV * HDIM];
__device__ __align__(128) float g_Vt[(size_t)HEADS * LKV * HDIM];

static __device__ __forceinline__ uint32_t f2tf(float x){
    uint32_t r; asm("cvt.rna.tf32.f32 %0, %1;" : "=r"(r) : "f"(x)); return r;
}
static __device__ __forceinline__ float tf32r(float x){ return __uint_as_float(f2tf(x)); }
static __device__ __forceinline__ float ex2(float x){
    float y; asm("ex2.approx.ftz.f32 %0, %1;" : "=f"(y) : "f"(x)); return y;
}

// RoPE cos/sin for channel pair p (channels 2p,2p+1). ROPE_DIMS=(16,56,56), theta=256=2^8.
static __device__ __forceinline__ void rope_cs(int p, int pt, int ph, int pw, float& c, float& s){
    float ang;
    if (p < 8)       ang = (float)pt * exp2f(-(float)p);
    else if (p < 36) ang = (float)ph * exp2f(-16.0f * (float)(p - 8)  / 56.0f);
    else             ang = (float)pw * exp2f(-16.0f * (float)(p - 36) / 56.0f);
    sincosf(ang, &s, &c);
}

// ---------------- staging: Q (rope + tile) ----------------
__global__ void stage_q_kernel(const float* __restrict__ q){
    long long idx = (long long)blockIdx.x * 256 + threadIdx.x;   // (l, h, pair)
    int p = (int)(idx & 63);
    int h = (int)((idx >> 6) % HEADS);
    int l = (int)(idx / (64 * HEADS));
    if (l >= LQ) return;
    int t = l / 1152, hh = (l / 48) % 24, w = l % 48;
    const float2 x = *(const float2*)(q + ((size_t)l * HEADS + h) * HDIM + 2 * p);
    float c, s; rope_cs(p, t, hh, w, c, s);
    int row = (((t >> 2) * 3 + (hh >> 3)) * 6 + (w >> 3)) * 256
            + (t & 3) * 64 + (hh & 7) * 8 + (w & 7);
    *(float2*)(g_Qt + ((size_t)h * LQ + row) * HDIM + 2 * p) =
        make_float2(x.x * c - x.y * s, x.y * c + x.x * s);
}

// ---------------- staging: K (wrap + rope, tf32) and V (wrap, tf32), tiled ----------------
__global__ void stage_kv_kernel(const float* __restrict__ k, const float* __restrict__ v){
    long long idx = (long long)blockIdx.x * 256 + threadIdx.x;
    int p = (int)(idx & 63);
    int h = (int)((idx >> 6) % HEADS);
    int j = (int)(idx / (64 * HEADS));           // glued linear over (12,40,64)
    if (j >= LKV) return;
    int jt = j / 2560, jh = (j / 64) % 40, jw = j % 64;
    int ho = (jh + 16) % 24;                     // (jh-8) mod 24
    int wo = (jw + 40) % 48;                     // (jw-8) mod 48
    size_t src = ((size_t)((jt * 24 + ho) * 48 + wo) * HEADS + h) * HDIM + 2 * p;
    const float2 xk = *(const float2*)(k + src);
    const float2 xv = *(const float2*)(v + src);
    float c, s; rope_cs(p, jt, jh - 8, jw - 8, c, s);
    int row = (((jt >> 2) * 5 + (jh >> 3)) * 8 + (jw >> 3)) * 256
            + (jt & 3) * 64 + (jh & 7) * 8 + (jw & 7);
    size_t dst = ((size_t)h * LKV + row) * HDIM + 2 * p;
    *(float2*)(g_Kt + dst) = make_float2(tf32r(xk.x * c - xk.y * s), tf32r(xk.y * c + xk.x * s));
    *(float2*)(g_Vt + dst) = make_float2(tf32r(xv.x), tf32r(xv.y));
}

// ---------------- attention ----------------
#define KROW 132                 // K smem row stride (floats): 132 mod 32 == 4
#define VROW 136                 // V smem row stride: 136 mod 32 == 8
#define PROW 68                  // P smem row stride: 68 mod 32 == 4
#define KS_FLOATS (64 * KROW)
#define VS_FLOATS (64 * VROW)
#define PS_FLOATS (128 * PROW)
#define SMEM_BYTES ((2 * KS_FLOATS + 2 * VS_FLOATS + PS_FLOATS) * 4)

static __device__ __forceinline__ void mma_tf32(float* c, const uint32_t* a, uint32_t b0, uint32_t b1){
    asm volatile(
        "mma.sync.aligned.m16n8k8.row.col.f32.tf32.tf32.f32 "
        "{%0,%1,%2,%3}, {%4,%5,%6,%7}, {%8,%9}, {%0,%1,%2,%3};"
        : "+f"(c[0]), "+f"(c[1]), "+f"(c[2]), "+f"(c[3])
        : "r"(a[0]), "r"(a[1]), "r"(a[2]), "r"(a[3]), "r"(b0), "r"(b1));
}
static __device__ __forceinline__ void cpa16(float* dst, const float* src){
    uint32_t d = (uint32_t)__cvta_generic_to_shared(dst);
    asm volatile("cp.async.cg.shared.global [%0], [%1], 16;" :: "r"(d), "l"(src));
}

static __device__ __forceinline__ void prefetch_chunk(
    int it, int head, int qbh, int qbw, int tid, float* KsB, float* VsB){
    int kbi = it >> 2, ch = it & 3;
    int kt = kbi / 9, rr = kbi % 9;
    int kvb = (kt * 5 + qbh + rr / 3) * 8 + (qbw + rr % 3);
    size_t off = ((size_t)head * LKV + kvb * 256 + ch * 64) * HDIM;
    const float* Ksrc = g_Kt + off;
    const float* Vsrc = g_Vt + off;
    float* Kd = KsB + (it & 1) * KS_FLOATS;
    float* Vd = VsB + (it & 1) * VS_FLOATS;
    #pragma unroll
    for (int i = 0; i < 8; i++){
        int idx = tid + i * 256, r = idx >> 5, c = idx & 31;
        cpa16(Kd + r * KROW + c * 4, Ksrc + r * HDIM + c * 4);
        cpa16(Vd + r * VROW + c * 4, Vsrc + r * HDIM + c * 4);
    }
    asm volatile("cp.async.commit_group;" ::: "memory");
}

__global__ void __launch_bounds__(256, 1) attn_kernel(float* __restrict__ out){
    extern __shared__ float sm[];
    float* KsB = sm;
    float* VsB = sm + 2 * KS_FLOATS;
    float* Ps  = VsB + 2 * VS_FLOATS;
    const int tid = threadIdx.x, lane = tid & 31, wp = tid >> 5;
    const int tig = lane & 3, rq = lane >> 2;
    const int head = blockIdx.y;
    const int qb = blockIdx.x >> 1, hf = blockIdx.x & 1;
    const int qbw = qb % 6, qbh = (qb / 6) % 3, qbt = qb / 18;
    const int r0 = qb * 256 + hf * 128 + wp * 16 + rq;

    // Q -> tf32 A fragments, pre-scaled by (1/sqrt(128)) * log2(e)
    const float SC = 0.08838834764831845f * 1.4426950408889634f;
    const float* Qp = g_Qt + ((size_t)head * LQ + r0) * HDIM;
    uint32_t qa[16][4];
    #pragma unroll
    for (int kc = 0; kc < 16; kc++){
        int c0 = 8 * kc + tig;
        qa[kc][0] = f2tf(Qp[c0] * SC);
        qa[kc][1] = f2tf(Qp[8 * HDIM + c0] * SC);
        qa[kc][2] = f2tf(Qp[c0 + 4] * SC);
        qa[kc][3] = f2tf(Qp[8 * HDIM + c0 + 4] * SC);
    }

    float o[16][4];
    #pragma unroll
    for (int i = 0; i < 16; i++){ o[i][0]=o[i][1]=o[i][2]=o[i][3]=0.f; }
    float m0 = -1e30f, m1 = -1e30f, l0 = 0.f, l1 = 0.f;
    float* PsW = Ps + wp * (16 * PROW);

    prefetch_chunk(0, head, qbh, qbw, tid, KsB, VsB);

    for (int it = 0; it < NITER; it++){
        asm volatile("cp.async.wait_all;" ::: "memory");
        __syncthreads();
        if (it + 1 < NITER) prefetch_chunk(it + 1, head, qbh, qbw, tid, KsB, VsB);
        const float* Kc = KsB + (it & 1) * KS_FLOATS;
        const float* Vc = VsB + (it & 1) * VS_FLOATS;

        // ---- S = Q K^T  (16 q rows x 64 keys per warp) ----
        float s[8][4];
        #pragma unroll
        for (int nt = 0; nt < 8; nt++){ s[nt][0]=s[nt][1]=s[nt][2]=s[nt][3]=0.f; }
        #pragma unroll
        for (int kc = 0; kc < 16; kc++){
            #pragma unroll
            for (int nt = 0; nt < 8; nt++){
                const float* bp = Kc + (nt * 8 + rq) * KROW + 8 * kc + tig;
                mma_tf32(s[nt], qa[kc], __float_as_uint(bp[0]), __float_as_uint(bp[4]));
            }
        }

        // ---- online softmax (exp2 domain) ----
        float mx0 = -1e30f, mx1 = -1e30f;
        #pragma unroll
        for (int nt = 0; nt < 8; nt++){
            mx0 = fmaxf(mx0, fmaxf(s[nt][0], s[nt][1]));
            mx1 = fmaxf(mx1, fmaxf(s[nt][2], s[nt][3]));
        }
        mx0 = fmaxf(mx0, __shfl_xor_sync(~0u, mx0, 1));
        mx0 = fmaxf(mx0, __shfl_xor_sync(~0u, mx0, 2));
        mx1 = fmaxf(mx1, __shfl_xor_sync(~0u, mx1, 1));
        mx1 = fmaxf(mx1, __shfl_xor_sync(~0u, mx1, 2));
        float mn0 = fmaxf(m0, mx0), mn1 = fmaxf(m1, mx1);
        float cor0 = ex2(m0 - mn0), cor1 = ex2(m1 - mn1);
        m0 = mn0; m1 = mn1;

        float sum0 = 0.f, sum1 = 0.f;
        #pragma unroll
        for (int nt = 0; nt < 8; nt++){
            float p0 = ex2(s[nt][0] - mn0), p1 = ex2(s[nt][1] - mn0);
            float p2 = ex2(s[nt][2] - mn1), p3 = ex2(s[nt][3] - mn1);
            sum0 += p0 + p1; sum1 += p2 + p3;
            int cc = nt * 8 + 2 * tig;
            *(float2*)(PsW + rq * PROW + cc)       = make_float2(tf32r(p0), tf32r(p1));
            *(float2*)(PsW + (rq + 8) * PROW + cc) = make_float2(tf32r(p2), tf32r(p3));
        }
        sum0 += __shfl_xor_sync(~0u, sum0, 1);
        sum0 += __shfl_xor_sync(~0u, sum0, 2);
        sum1 += __shfl_xor_sync(~0u, sum1, 1);
        sum1 += __shfl_xor_sync(~0u, sum1, 2);
        l0 = l0 * cor0 + sum0;
        l1 = l1 * cor1 + sum1;
        #pragma unroll
        for (int nt = 0; nt < 16; nt++){
            o[nt][0] *= cor0; o[nt][1] *= cor0; o[nt][2] *= cor1; o[nt][3] *= cor1;
        }
        __syncwarp();

        // ---- O += P V  (k = keys, chunks of 8) ----
        #pragma unroll
        for (int kk = 0; kk < 8; kk++){
            uint32_t pa[4];
            int c0 = 8 * kk + tig;
            pa[0] = __float_as_uint(PsW[rq * PROW + c0]);
            pa[1] = __float_as_uint(PsW[(rq + 8) * PROW + c0]);
            pa[2] = __float_as_uint(PsW[rq * PROW + c0 + 4]);
            pa[3] = __float_as_uint(PsW[(rq + 8) * PROW + c0 + 4]);
            #pragma unroll
            for (int nt = 0; nt < 16; nt++){
                const float* vp = Vc + (8 * kk + tig) * VROW + nt * 8 + rq;
                mma_tf32(o[nt], pa, __float_as_uint(vp[0]), __float_as_uint(vp[4 * VROW]));
            }
        }
        __syncwarp();
    }

    // ---- epilogue: normalize + scatter back to canvas layout ----
    const int local0 = hf * 128 + wp * 16 + rq;
    #pragma unroll
    for (int half = 0; half < 2; half++){
        int local = local0 + half * 8;
        float inv = 1.f / (half ? l1 : l0);
        int lt = local >> 6, lh = (local >> 3) & 7, lw = local & 7;
        int t = qbt * 4 + lt, hh = qbh * 8 + lh, w = qbw * 8 + lw;
        size_t base = ((size_t)((t * 24 + hh) * 48 + w) * HEADS + head) * HDIM;
        #pragma unroll
        for (int nt = 0; nt < 16; nt++){
            *(float2*)(out + base + nt * 8 + 2 * tig) =
                make_float2(o[nt][2 * half] * inv, o[nt][2 * half + 1] * inv);
        }
    }
}

extern "C" void kernel_launch(void* const* d_in, const int* in_sizes, int n_in,
                              void* d_out, int out_size) {
    const float* q = (const float*)d_in[0];
    const float* k = (const float*)d_in[1];
    const float* v = (const float*)d_in[2];
    float* out = (float*)d_out;
    (void)in_sizes; (void)n_in; (void)out_size;

    stage_q_kernel<<<(LQ * HEADS * 64) / 256, 256>>>(q);
    stage_kv_kernel<<<(LKV * HEADS * 64) / 256, 256>>>(k, v);

    cudaFuncSetAttribute(attn_kernel, cudaFuncAttributeMaxDynamicSharedMemorySize, SMEM_BYTES);
    attn_kernel<<<dim3(108, HEADS), 256, SMEM_BYTES>>>(out);
}